// round 15
// baseline (speedup 1.0000x reference)
#include <cuda_runtime.h>
#include <cuda_fp16.h>
#include <cstdint>
#include <math.h>

#define S_LEN   2048
#define DM      1024
#define NHEADS  16
#define HDIM    64
#define BATCH   2
#define MROWS   (BATCH * S_LEN)   // 4096

// ---------------------------------------------------------------------------
// Scratch (device globals; no runtime allocation allowed)
// ---------------------------------------------------------------------------
__device__ __align__(256) __half g_qkvh[MROWS * 3 * DM];
__device__ __align__(256) __half g_xh[MROWS * DM];
__device__ __align__(256) __half g_ctxh[MROWS * DM];
__device__ __align__(256) __half g_wqkvTh[3 * DM * DM];     // Wqkv^T [3072,1024] fp16
__device__ __align__(256) __half g_woutTh[DM * DM];         // Wout^T fp16

// ---------------------------------------------------------------------------
// Helpers
// ---------------------------------------------------------------------------
__device__ __forceinline__ uint32_t smem_to_u32(const void* p) {
    uint32_t a;
    asm("{ .reg .u64 t; cvta.to.shared.u64 t, %1; cvt.u32.u64 %0, t; }" : "=r"(a) : "l"(p));
    return a;
}
#define SMEM_SWIZZLE_128B(off) ((off) ^ (((off) >> 3) & 0x70))

__device__ __forceinline__ void cp16(uint32_t dst, const void* src) {
    asm volatile("cp.async.cg.shared.global [%0], [%1], 16;" :: "r"(dst), "l"(src));
}
#define CP_COMMIT()    asm volatile("cp.async.commit_group;" ::: "memory")
#define CP_WAIT(n)     asm volatile("cp.async.wait_group %0;" :: "n"(n) : "memory")

__device__ __forceinline__ void ldsm_x4(uint32_t (&r)[4], uint32_t addr) {
    asm volatile("ldmatrix.sync.aligned.m8n8.x4.shared.b16 {%0,%1,%2,%3}, [%4];"
        : "=r"(r[0]), "=r"(r[1]), "=r"(r[2]), "=r"(r[3]) : "r"(addr));
}
__device__ __forceinline__ void ldsm_x4_t(uint32_t (&r)[4], uint32_t addr) {
    asm volatile("ldmatrix.sync.aligned.m8n8.x4.trans.shared.b16 {%0,%1,%2,%3}, [%4];"
        : "=r"(r[0]), "=r"(r[1]), "=r"(r[2]), "=r"(r[3]) : "r"(addr));
}
__device__ __forceinline__ void mma_f16(float (&c)[4], const uint32_t (&a)[4],
                                        uint32_t b0, uint32_t b1) {
    asm volatile("mma.sync.aligned.m16n8k16.row.col.f32.f16.f16.f32 "
        "{%0,%1,%2,%3}, {%4,%5,%6,%7}, {%8,%9}, {%0,%1,%2,%3};"
        : "+f"(c[0]), "+f"(c[1]), "+f"(c[2]), "+f"(c[3])
        : "r"(a[0]), "r"(a[1]), "r"(a[2]), "r"(a[3]), "r"(b0), "r"(b1));
}
__device__ __forceinline__ float fast_exp2(float x) {
    float y;
    asm("ex2.approx.ftz.f32 %0, %1;" : "=f"(y) : "f"(x));
    return y;
}
__device__ __forceinline__ uint32_t pack_h2(float v0, float v1) {
    __half2 hp = __floats2half2_rn(v0, v1);
    return *reinterpret_cast<uint32_t*>(&hp);
}

// ---------------------------------------------------------------------------
// Fused prologue: one launch.
//   blocks [0, XB):              round x -> fp16   (XB = 4096: 1M float4 / 256)
//   blocks [XB, XB+QB):          transpose+round Wqkv -> [3072,1024] fp16
//   blocks [XB+QB, XB+QB+OB):    transpose+round Wout -> [1024,1024] fp16
// ---------------------------------------------------------------------------
#define XB  4096                      // (4096*1024/4) / 256
#define QB  (96 * 32)                 // 3072/32 x 1024/32
#define OB  (32 * 32)

__global__ __launch_bounds__(256) void prologue(
    const float* __restrict__ x, __half* __restrict__ xh,
    const float* __restrict__ Wqkv, __half* __restrict__ wqT,
    const float* __restrict__ Wout, __half* __restrict__ woT)
{
    __shared__ float t[32][33];
    const int bid = blockIdx.x;
    const int tid = threadIdx.x;

    if (bid < XB) {
        int i = bid * 256 + tid;
        float4 v = reinterpret_cast<const float4*>(x)[i];
        uint2 o;
        o.x = pack_h2(v.x, v.y);
        o.y = pack_h2(v.z, v.w);
        reinterpret_cast<uint2*>(xh)[i] = o;
        return;
    }

    const float* W;
    __half* WT;
    int bx, by, N;
    if (bid < XB + QB) {
        int idx = bid - XB;
        W = Wqkv; WT = wqT; N = 3 * DM;
        bx = idx % 96; by = idx / 96;
    } else {
        int idx = bid - XB - QB;
        W = Wout; WT = woT; N = DM;
        bx = idx % 32; by = idx / 32;
    }
    const int kb = by * 32, nb = bx * 32;
    const int tx = tid & 31, ty0 = tid >> 5;
    #pragma unroll
    for (int r = ty0; r < 32; r += 8)
        t[r][tx] = W[(size_t)(kb + r) * N + nb + tx];
    __syncthreads();
    #pragma unroll
    for (int r = ty0; r < 32; r += 8)
        WT[(size_t)(nb + r) * DM + kb + tx] = __float2half(t[tx][r]);
}

// ---------------------------------------------------------------------------
// mma.sync fp16 single-pass GEMM + bias:  C = Ah @ Bh^T + bias
// CTA 128x128, BK=64 (128B rows, SW128), 2 stages, 8 warps of 64x32.
// MODE 0: f32 C.  MODE 1: fp16 Ch.
// ---------------------------------------------------------------------------
#define GS_TILE   16384                      // 128 rows x 64 fp16 (128B rows)
#define GS_STAGE  (2 * GS_TILE)              // 32768
#define GEMM_SMEM (2 * GS_STAGE)             // 65536

template<int MODE>
__global__ __launch_bounds__(256, 2) void gemm_mma(
    const __half* __restrict__ Ah, const __half* __restrict__ Bh,
    const float* __restrict__ bias, float* __restrict__ C,
    __half* __restrict__ Ch, int M, int N, int K)
{
    extern __shared__ char smem[];
    const uint32_t sb = smem_to_u32(smem);
    const int tid = threadIdx.x;
    const int wid = tid >> 5, lid = tid & 31;
    const int wm = wid & 1;
    const int wn = wid >> 1;
    const int m0 = blockIdx.y * 128, n0 = blockIdx.x * 128;

    float acc[4][4][4];
    #pragma unroll
    for (int i = 0; i < 4; i++)
        #pragma unroll
        for (int j = 0; j < 4; j++)
            #pragma unroll
            for (int r = 0; r < 4; r++) acc[i][j][r] = 0.0f;

    const int a_row  = (lid & 7) + ((lid >> 3) & 1) * 8;
    const int a_koff = (lid >> 4) << 3;
    const int b_row  = ((lid >> 4) << 3) + (lid & 7);
    const int b_koff = ((lid >> 3) & 1) << 3;

    const int nStages = K >> 6;   // BK=64

    auto load_stage = [&](int buf, int k0) {
        uint32_t sbase = sb + buf * GS_STAGE;
        #pragma unroll
        for (int t = 0; t < 2; ++t) {
            const __half* src = (t == 0) ? Ah : Bh;
            const int r0 = (t == 0) ? m0 : n0;
            #pragma unroll
            for (int p = 0; p < 4; ++p) {
                int idx = tid + p * 256;           // 0..1023
                int r = idx >> 3;                  // 0..127
                int c = (idx & 7) << 3;            // 0..56
                uint32_t off = (uint32_t)(r * 128 + c * 2);
                cp16(sbase + t * GS_TILE + SMEM_SWIZZLE_128B(off),
                     src + (size_t)(r0 + r) * K + k0 + c);
            }
        }
    };

    load_stage(0, 0);
    CP_COMMIT();

    for (int it = 0; it < nStages; ++it) {
        CP_WAIT(0);
        __syncthreads();
        if (it + 1 < nStages) {
            load_stage((it + 1) & 1, (it + 1) << 6);
            CP_COMMIT();
        }

        const uint32_t stage = sb + (it & 1) * GS_STAGE;
        #pragma unroll
        for (int ks = 0; ks < 4; ++ks) {
            const int kk = ks << 4;
            uint32_t ah[4][4], bb[2][4];
            #pragma unroll
            for (int mi = 0; mi < 4; ++mi) {
                int rg = wm * 64 + mi * 16 + a_row;
                uint32_t sw = (uint32_t)(rg * 128 + (kk + a_koff) * 2)
                              ^ ((uint32_t)(rg & 7) << 4);
                ldsm_x4(ah[mi], stage + sw);
            }
            #pragma unroll
            for (int g = 0; g < 2; ++g) {
                int rg = wn * 32 + g * 16 + b_row;
                uint32_t sw = (uint32_t)(rg * 128 + (kk + b_koff) * 2)
                              ^ ((uint32_t)(rg & 7) << 4);
                ldsm_x4(bb[g], stage + GS_TILE + sw);
            }
            #pragma unroll
            for (int mi = 0; mi < 4; ++mi)
                #pragma unroll
                for (int g = 0; g < 2; ++g) {
                    mma_f16(acc[mi][2 * g],     ah[mi], bb[g][0], bb[g][1]);
                    mma_f16(acc[mi][2 * g + 1], ah[mi], bb[g][2], bb[g][3]);
                }
        }
    }

    const int cg = lid >> 2, ct = lid & 3;
    #pragma unroll
    for (int mi = 0; mi < 4; ++mi) {
        #pragma unroll
        for (int ni = 0; ni < 4; ++ni) {
            int row = m0 + wm * 64 + mi * 16 + cg;
            int col = n0 + wn * 32 + ni * 8 + 2 * ct;
            float2 bv = *reinterpret_cast<const float2*>(&bias[col]);
            float v00 = acc[mi][ni][0] + bv.x, v01 = acc[mi][ni][1] + bv.y;
            float v10 = acc[mi][ni][2] + bv.x, v11 = acc[mi][ni][3] + bv.y;
            if (MODE == 0) {
                float2 o0 = {v00, v01}, o1 = {v10, v11};
                *reinterpret_cast<float2*>(&C[(size_t)row * N + col]) = o0;
                *reinterpret_cast<float2*>(&C[(size_t)(row + 8) * N + col]) = o1;
            } else {
                *reinterpret_cast<uint32_t*>(&Ch[(size_t)row * N + col]) =
                    pack_h2(v00, v01);
                *reinterpret_cast<uint32_t*>(&Ch[(size_t)(row + 8) * N + col]) =
                    pack_h2(v10, v11);
            }
        }
    }
}

// ---------------------------------------------------------------------------
// Tensor-core flash attention (fp16, single-pass S and PV).
// Block: (q-tile 128, b*h). 8 warps of 16 q-rows. cp.async 2-stage KV.
// ---------------------------------------------------------------------------
#define FTS_Q     0
#define FKV_BASE  16384
#define FKV_STAGE 16384      // Kh 8K + Vh 8K
#define FLASH_SMEM_TC (FKV_BASE + 2 * FKV_STAGE)   // 49152

__global__ __launch_bounds__(256, 2) void flash_tc(
    const __half* __restrict__ qkvh, __half* __restrict__ ctxh)
{
    extern __shared__ char smem[];
    const uint32_t sb = smem_to_u32(smem);
    const int tid = threadIdx.x;
    const int wid = tid >> 5, lid = tid & 31;
    const int bh = blockIdx.x;
    const int qt = (gridDim.y - 1) - blockIdx.y;    // heavy tiles first
    const int b = bh >> 4, h = bh & 15;
    const int q0 = qt * 128;
    const float LOG2E = 1.4426950408889634f;

    auto load_kv = [&](int buf, int k0) {
        uint32_t sbase = sb + FKV_BASE + buf * FKV_STAGE;
        #pragma unroll
        for (int t = 0; t < 2; ++t) {              // 0: Kh, 1: Vh
            const int coloff = (t == 0) ? DM : 2 * DM;
            #pragma unroll
            for (int p = 0; p < 2; ++p) {
                int idx = tid + p * 256;
                int r = idx >> 3;
                int c = (idx & 7) << 3;
                uint32_t off = (uint32_t)(r * 128 + c * 2);
                cp16(sbase + t * 8192 + SMEM_SWIZZLE_128B(off),
                     qkvh + (size_t)(b * S_LEN + k0 + r) * (3 * DM) + coloff + h * HDIM + c);
            }
        }
    };

    // Q tile into smem, swizzled
    #pragma unroll
    for (int p = 0; p < 4; ++p) {
        int idx = tid + p * 256;
        int r = idx >> 3;
        int c = (idx & 7) << 3;
        uint4 v = *reinterpret_cast<const uint4*>(
            qkvh + (size_t)(b * S_LEN + q0 + r) * (3 * DM) + h * HDIM + c);
        uint32_t off = (uint32_t)(r * 128 + c * 2);
        *reinterpret_cast<uint4*>(smem + FTS_Q + SMEM_SWIZZLE_128B(off)) = v;
    }
    load_kv(0, 0);
    CP_COMMIT();
    __syncthreads();

    const int a_row  = (lid & 7) + ((lid >> 3) & 1) * 8;
    const int a_koff = (lid >> 4) << 3;
    const int b_row  = ((lid >> 4) << 3) + (lid & 7);
    const int b_koff = ((lid >> 3) & 1) << 3;
    uint32_t qh[4][4];
    #pragma unroll
    for (int kk = 0; kk < 4; ++kk) {
        int rg = wid * 16 + a_row;
        uint32_t sw = (uint32_t)(rg * 128 + (kk * 16 + a_koff) * 2)
                      ^ ((uint32_t)(rg & 7) << 4);
        ldsm_x4(qh[kk], sb + FTS_Q + sw);
    }

    float o[8][4];
    #pragma unroll
    for (int j = 0; j < 8; ++j)
        #pragma unroll
        for (int r = 0; r < 4; ++r) o[j][r] = 0.0f;
    float mrow[2] = {-INFINITY, -INFINITY};
    float lrow[2] = {0.0f, 0.0f};

    const int g8 = lid >> 2, t2 = (lid & 3) * 2;
    const int nkt = 2 * qt + 2;

    for (int kt = 0; kt < nkt; ++kt) {
        const int k0 = kt * 64;
        CP_WAIT(0);
        __syncthreads();
        if (kt + 1 < nkt) {
            load_kv((kt + 1) & 1, (kt + 1) * 64);
            CP_COMMIT();
        }

        const uint32_t kvs = sb + FKV_BASE + (kt & 1) * FKV_STAGE;

        if (q0 + wid * 16 + 15 >= k0) {
            float s[8][4];
            #pragma unroll
            for (int j = 0; j < 8; ++j)
                #pragma unroll
                for (int r = 0; r < 4; ++r) s[j][r] = 0.0f;

            // S = Qh @ Kh^T (single pass)
            #pragma unroll
            for (int kk = 0; kk < 4; ++kk) {
                uint32_t kb[4][4];
                #pragma unroll
                for (int g = 0; g < 4; ++g) {
                    int rg = g * 16 + b_row;
                    uint32_t sw = (uint32_t)(rg * 128 + (kk * 16 + b_koff) * 2)
                                  ^ ((uint32_t)(rg & 7) << 4);
                    ldsm_x4(kb[g], kvs + sw);
                }
                #pragma unroll
                for (int g = 0; g < 4; ++g) {
                    mma_f16(s[2 * g],     qh[kk], kb[g][0], kb[g][1]);
                    mma_f16(s[2 * g + 1], qh[kk], kb[g][2], kb[g][3]);
                }
            }

            const bool diag = (k0 + 63 > q0 + wid * 16);
            #pragma unroll
            for (int j = 0; j < 8; ++j) {
                #pragma unroll
                for (int r2 = 0; r2 < 2; ++r2) {
                    int qrow = q0 + wid * 16 + g8 + 8 * r2;
                    #pragma unroll
                    for (int e = 0; e < 2; ++e) {
                        float v = s[j][2 * r2 + e] * 0.125f;
                        if (diag && (k0 + j * 8 + t2 + e > qrow)) v = -1e30f;
                        s[j][2 * r2 + e] = v;
                    }
                }
            }

            #pragma unroll
            for (int r2 = 0; r2 < 2; ++r2) {
                float mx = -INFINITY;
                #pragma unroll
                for (int j = 0; j < 8; ++j)
                    mx = fmaxf(mx, fmaxf(s[j][2 * r2], s[j][2 * r2 + 1]));
                mx = fmaxf(mx, __shfl_xor_sync(0xffffffffu, mx, 1));
                mx = fmaxf(mx, __shfl_xor_sync(0xffffffffu, mx, 2));
                float mnew = fmaxf(mrow[r2], mx);
                float alpha = fast_exp2((mrow[r2] - mnew) * LOG2E);
                mrow[r2] = mnew;
                float ls = 0.0f;
                #pragma unroll
                for (int j = 0; j < 8; ++j) {
                    float p0 = fast_exp2((s[j][2 * r2] - mnew) * LOG2E);
                    float p1 = fast_exp2((s[j][2 * r2 + 1] - mnew) * LOG2E);
                    s[j][2 * r2] = p0;
                    s[j][2 * r2 + 1] = p1;
                    ls += p0 + p1;
                }
                ls += __shfl_xor_sync(0xffffffffu, ls, 1);
                ls += __shfl_xor_sync(0xffffffffu, ls, 2);
                lrow[r2] = lrow[r2] * alpha + ls;
                #pragma unroll
                for (int j = 0; j < 8; ++j) {
                    o[j][2 * r2] *= alpha;
                    o[j][2 * r2 + 1] *= alpha;
                }
            }

            // O += Ph @ Vh (single pass)
            #pragma unroll
            for (int kk = 0; kk < 4; ++kk) {
                uint32_t ph[4];
                ph[0] = pack_h2(s[2 * kk][0],     s[2 * kk][1]);
                ph[1] = pack_h2(s[2 * kk][2],     s[2 * kk][3]);
                ph[2] = pack_h2(s[2 * kk + 1][0], s[2 * kk + 1][1]);
                ph[3] = pack_h2(s[2 * kk + 1][2], s[2 * kk + 1][3]);
                int vrow = kk * 16 + (lid & 7) + ((lid >> 3) & 1) * 8;
                uint32_t vb[4][4];
                #pragma unroll
                for (int j2 = 0; j2 < 4; ++j2) {
                    uint32_t sw = (uint32_t)(vrow * 128 + j2 * 32 + ((lid >> 4) & 1) * 16)
                                  ^ ((uint32_t)(vrow & 7) << 4);
                    ldsm_x4_t(vb[j2], kvs + 8192 + sw);
                }
                #pragma unroll
                for (int j2 = 0; j2 < 4; ++j2) {
                    mma_f16(o[2 * j2],     ph, vb[j2][0], vb[j2][1]);
                    mma_f16(o[2 * j2 + 1], ph, vb[j2][2], vb[j2][3]);
                }
            }
        }
    }

    float inv0 = 1.0f / lrow[0], inv1 = 1.0f / lrow[1];
    size_t row0 = (size_t)(b * S_LEN + q0 + wid * 16 + g8);
    #pragma unroll
    for (int j = 0; j < 8; ++j) {
        int c = h * HDIM + j * 8 + t2;
        *reinterpret_cast<uint32_t*>(&ctxh[row0 * DM + c]) =
            pack_h2(o[j][0] * inv0, o[j][1] * inv0);
        *reinterpret_cast<uint32_t*>(&ctxh[(row0 + 8) * DM + c]) =
            pack_h2(o[j][2] * inv1, o[j][3] * inv1);
    }
}

// ---------------------------------------------------------------------------
extern "C" void kernel_launch(void* const* d_in, const int* in_sizes, int n_in,
                              void* d_out, int out_size)
{
    const float* x    = (const float*)d_in[0];
    const float* Wqkv = (const float*)d_in[1];
    const float* bqkv = (const float*)d_in[2];
    const float* Wout = (const float*)d_in[3];
    const float* bout = (const float*)d_in[4];
    float* out = (float*)d_out;

    __half *qkvh, *xh, *ctxh, *wqh, *woh;
    cudaGetSymbolAddress((void**)&qkvh, g_qkvh);
    cudaGetSymbolAddress((void**)&xh, g_xh);
    cudaGetSymbolAddress((void**)&ctxh, g_ctxh);
    cudaGetSymbolAddress((void**)&wqh, g_wqkvTh);
    cudaGetSymbolAddress((void**)&woh, g_woutTh);

    cudaFuncSetAttribute(gemm_mma<0>, cudaFuncAttributeMaxDynamicSharedMemorySize, GEMM_SMEM);
    cudaFuncSetAttribute(gemm_mma<1>, cudaFuncAttributeMaxDynamicSharedMemorySize, GEMM_SMEM);
    cudaFuncSetAttribute(flash_tc, cudaFuncAttributeMaxDynamicSharedMemorySize, FLASH_SMEM_TC);

    // 0) Fused prologue: round x + transpose/round both weights (one launch)
    prologue<<<XB + QB + OB, 256>>>(x, xh, Wqkv, wqh, Wout, woh);

    // 1) QKV projection (single pass) -> fp16 qkv
    gemm_mma<1><<<dim3(3 * DM / 128, MROWS / 128), 256, GEMM_SMEM>>>(
        xh, wqh, bqkv, nullptr, qkvh, MROWS, 3 * DM, DM);

    // 2) Causal flash attention -> fp16 ctx
    flash_tc<<<dim3(BATCH * NHEADS, S_LEN / 128), 256, FLASH_SMEM_TC>>>(qkvh, ctxh);

    // 3) Output projection (single pass) -> f32 out
    gemm_mma<0><<<dim3(DM / 128, MROWS / 128), 256, GEMM_SMEM>>>(
        ctxh, woh, bout, out, nullptr, MROWS, DM, DM);
}

// round 16
// speedup vs baseline: 1.4629x; 1.4629x over previous
#include <cuda_runtime.h>
#include <cuda_fp16.h>
#include <cstdint>
#include <math.h>

#define S_LEN   2048
#define DM      1024
#define NHEADS  16
#define HDIM    64
#define BATCH   2
#define MROWS   (BATCH * S_LEN)   // 4096

// ---------------------------------------------------------------------------
// Scratch (device globals; no runtime allocation allowed)
// ---------------------------------------------------------------------------
__device__ __align__(256) __half g_qkvh[MROWS * 3 * DM];
__device__ __align__(256) __half g_xh[MROWS * DM];
__device__ __align__(256) __half g_ctxh[MROWS * DM];
__device__ __align__(256) __half g_wqkvTh[3 * DM * DM];     // Wqkv^T [3072,1024] fp16
__device__ __align__(256) __half g_woutTh[DM * DM];         // Wout^T fp16

// ---------------------------------------------------------------------------
// Helpers
// ---------------------------------------------------------------------------
__device__ __forceinline__ uint32_t smem_to_u32(const void* p) {
    uint32_t a;
    asm("{ .reg .u64 t; cvta.to.shared.u64 t, %1; cvt.u32.u64 %0, t; }" : "=r"(a) : "l"(p));
    return a;
}
#define SMEM_SWIZZLE_128B(off) ((off) ^ (((off) >> 3) & 0x70))
#define SMEM_SWIZZLE_64B(off)  ((off) ^ (((off) >> 3) & 0x30))

__device__ __forceinline__ void cp16(uint32_t dst, const void* src) {
    asm volatile("cp.async.cg.shared.global [%0], [%1], 16;" :: "r"(dst), "l"(src));
}
#define CP_COMMIT()    asm volatile("cp.async.commit_group;" ::: "memory")
#define CP_WAIT(n)     asm volatile("cp.async.wait_group %0;" :: "n"(n) : "memory")

__device__ __forceinline__ void ldsm_x4(uint32_t (&r)[4], uint32_t addr) {
    asm volatile("ldmatrix.sync.aligned.m8n8.x4.shared.b16 {%0,%1,%2,%3}, [%4];"
        : "=r"(r[0]), "=r"(r[1]), "=r"(r[2]), "=r"(r[3]) : "r"(addr));
}
__device__ __forceinline__ void ldsm_x4_t(uint32_t (&r)[4], uint32_t addr) {
    asm volatile("ldmatrix.sync.aligned.m8n8.x4.trans.shared.b16 {%0,%1,%2,%3}, [%4];"
        : "=r"(r[0]), "=r"(r[1]), "=r"(r[2]), "=r"(r[3]) : "r"(addr));
}
__device__ __forceinline__ void mma_f16(float (&c)[4], const uint32_t (&a)[4],
                                        uint32_t b0, uint32_t b1) {
    asm volatile("mma.sync.aligned.m16n8k16.row.col.f32.f16.f16.f32 "
        "{%0,%1,%2,%3}, {%4,%5,%6,%7}, {%8,%9}, {%0,%1,%2,%3};"
        : "+f"(c[0]), "+f"(c[1]), "+f"(c[2]), "+f"(c[3])
        : "r"(a[0]), "r"(a[1]), "r"(a[2]), "r"(a[3]), "r"(b0), "r"(b1));
}
__device__ __forceinline__ float fast_exp2(float x) {
    float y;
    asm("ex2.approx.ftz.f32 %0, %1;" : "=f"(y) : "f"(x));
    return y;
}
__device__ __forceinline__ uint32_t pack_h2(float v0, float v1) {
    __half2 hp = __floats2half2_rn(v0, v1);
    return *reinterpret_cast<uint32_t*>(&hp);
}

// ---------------------------------------------------------------------------
// Fused prologue: one launch.
//   blocks [0, XB):              round x -> fp16   (XB = 4096: 1M float4 / 256)
//   blocks [XB, XB+QB):          transpose+round Wqkv -> [3072,1024] fp16
//   blocks [XB+QB, XB+QB+OB):    transpose+round Wout -> [1024,1024] fp16
// ---------------------------------------------------------------------------
#define XB  4096                      // (4096*1024/4) / 256
#define QB  (96 * 32)                 // 3072/32 x 1024/32
#define OB  (32 * 32)

__global__ __launch_bounds__(256) void prologue(
    const float* __restrict__ x, __half* __restrict__ xh,
    const float* __restrict__ Wqkv, __half* __restrict__ wqT,
    const float* __restrict__ Wout, __half* __restrict__ woT)
{
    __shared__ float t[32][33];
    const int bid = blockIdx.x;
    const int tid = threadIdx.x;

    if (bid < XB) {
        int i = bid * 256 + tid;
        float4 v = reinterpret_cast<const float4*>(x)[i];
        uint2 o;
        o.x = pack_h2(v.x, v.y);
        o.y = pack_h2(v.z, v.w);
        reinterpret_cast<uint2*>(xh)[i] = o;
        return;
    }

    const float* W;
    __half* WT;
    int bx, by, N;
    if (bid < XB + QB) {
        int idx = bid - XB;
        W = Wqkv; WT = wqT; N = 3 * DM;
        bx = idx % 96; by = idx / 96;
    } else {
        int idx = bid - XB - QB;
        W = Wout; WT = woT; N = DM;
        bx = idx % 32; by = idx / 32;
    }
    const int kb = by * 32, nb = bx * 32;
    const int tx = tid & 31, ty0 = tid >> 5;
    #pragma unroll
    for (int r = ty0; r < 32; r += 8)
        t[r][tx] = W[(size_t)(kb + r) * N + nb + tx];
    __syncthreads();
    #pragma unroll
    for (int r = ty0; r < 32; r += 8)
        WT[(size_t)(nb + r) * DM + kb + tx] = __float2half(t[tx][r]);
}

// ---------------------------------------------------------------------------
// mma.sync fp16 single-pass GEMM + bias:  C = Ah @ Bh^T + bias
// CTA 128x128, BK=32 (64B rows, SW64), 2 stages, 8 warps of 64x32.
// MODE 0: f32 C.  MODE 1: fp16 Ch.    (proven R12 configuration)
// ---------------------------------------------------------------------------
#define GS_TILE   8192
#define GS_STAGE  (2 * GS_TILE)              // 16384
#define GEMM_SMEM (2 * GS_STAGE)             // 32768

template<int MODE>
__global__ __launch_bounds__(256, 2) void gemm_mma(
    const __half* __restrict__ Ah, const __half* __restrict__ Bh,
    const float* __restrict__ bias, float* __restrict__ C,
    __half* __restrict__ Ch, int M, int N, int K)
{
    extern __shared__ char smem[];
    const uint32_t sb = smem_to_u32(smem);
    const int tid = threadIdx.x;
    const int wid = tid >> 5, lid = tid & 31;
    const int wm = wid & 1;
    const int wn = wid >> 1;
    const int m0 = blockIdx.y * 128, n0 = blockIdx.x * 128;

    float acc[4][4][4];
    #pragma unroll
    for (int i = 0; i < 4; i++)
        #pragma unroll
        for (int j = 0; j < 4; j++)
            #pragma unroll
            for (int r = 0; r < 4; r++) acc[i][j][r] = 0.0f;

    const int a_row  = (lid & 7) + ((lid >> 3) & 1) * 8;
    const int a_koff = (lid >> 4) << 3;
    const int b_row  = ((lid >> 4) << 3) + (lid & 7);
    const int b_koff = ((lid >> 3) & 1) << 3;

    const int nStages = K >> 5;

    auto load_stage = [&](int buf, int k0) {
        uint32_t sbase = sb + buf * GS_STAGE;
        #pragma unroll
        for (int t = 0; t < 2; ++t) {
            const __half* src = (t == 0) ? Ah : Bh;
            const int r0 = (t == 0) ? m0 : n0;
            #pragma unroll
            for (int p = 0; p < 2; ++p) {
                int idx = tid + p * 256;
                int r = idx >> 2;
                int c = (idx & 3) << 3;
                uint32_t off = (uint32_t)(r * 64 + c * 2);
                cp16(sbase + t * GS_TILE + SMEM_SWIZZLE_64B(off),
                     src + (size_t)(r0 + r) * K + k0 + c);
            }
        }
    };

    load_stage(0, 0);
    CP_COMMIT();

    for (int it = 0; it < nStages; ++it) {
        CP_WAIT(0);
        __syncthreads();
        if (it + 1 < nStages) {
            load_stage((it + 1) & 1, (it + 1) << 5);
            CP_COMMIT();
        }

        const uint32_t stage = sb + (it & 1) * GS_STAGE;
        #pragma unroll
        for (int ks = 0; ks < 2; ++ks) {
            const int kk = ks << 4;
            uint32_t ah[4][4], bb[2][4];
            #pragma unroll
            for (int mi = 0; mi < 4; ++mi) {
                int rg = wm * 64 + mi * 16 + a_row;
                uint32_t off = SMEM_SWIZZLE_64B((uint32_t)(rg * 64 + (kk + a_koff) * 2));
                ldsm_x4(ah[mi], stage + off);
            }
            #pragma unroll
            for (int g = 0; g < 2; ++g) {
                int rg = wn * 32 + g * 16 + b_row;
                uint32_t off = (uint32_t)(rg * 64 + (kk + b_koff) * 2);
                ldsm_x4(bb[g], stage + GS_TILE + SMEM_SWIZZLE_64B(off));
            }
            #pragma unroll
            for (int mi = 0; mi < 4; ++mi)
                #pragma unroll
                for (int g = 0; g < 2; ++g) {
                    mma_f16(acc[mi][2 * g],     ah[mi], bb[g][0], bb[g][1]);
                    mma_f16(acc[mi][2 * g + 1], ah[mi], bb[g][2], bb[g][3]);
                }
        }
    }

    const int cg = lid >> 2, ct = lid & 3;
    #pragma unroll
    for (int mi = 0; mi < 4; ++mi) {
        #pragma unroll
        for (int ni = 0; ni < 4; ++ni) {
            int row = m0 + wm * 64 + mi * 16 + cg;
            int col = n0 + wn * 32 + ni * 8 + 2 * ct;
            float2 bv = *reinterpret_cast<const float2*>(&bias[col]);
            float v00 = acc[mi][ni][0] + bv.x, v01 = acc[mi][ni][1] + bv.y;
            float v10 = acc[mi][ni][2] + bv.x, v11 = acc[mi][ni][3] + bv.y;
            if (MODE == 0) {
                float2 o0 = {v00, v01}, o1 = {v10, v11};
                *reinterpret_cast<float2*>(&C[(size_t)row * N + col]) = o0;
                *reinterpret_cast<float2*>(&C[(size_t)(row + 8) * N + col]) = o1;
            } else {
                *reinterpret_cast<uint32_t*>(&Ch[(size_t)row * N + col]) =
                    pack_h2(v00, v01);
                *reinterpret_cast<uint32_t*>(&Ch[(size_t)(row + 8) * N + col]) =
                    pack_h2(v10, v11);
            }
        }
    }
}

// ---------------------------------------------------------------------------
// Tensor-core flash attention (fp16, single-pass S and PV).
// Block: (q-tile 128, b*h). 8 warps of 16 q-rows. cp.async 2-stage KV.
// ---------------------------------------------------------------------------
#define FTS_Q     0
#define FKV_BASE  16384
#define FKV_STAGE 16384      // Kh 8K + Vh 8K
#define FLASH_SMEM_TC (FKV_BASE + 2 * FKV_STAGE)   // 49152

__global__ __launch_bounds__(256, 2) void flash_tc(
    const __half* __restrict__ qkvh, __half* __restrict__ ctxh)
{
    extern __shared__ char smem[];
    const uint32_t sb = smem_to_u32(smem);
    const int tid = threadIdx.x;
    const int wid = tid >> 5, lid = tid & 31;
    const int bh = blockIdx.x;
    const int qt = (gridDim.y - 1) - blockIdx.y;    // heavy tiles first
    const int b = bh >> 4, h = bh & 15;
    const int q0 = qt * 128;
    const float LOG2E = 1.4426950408889634f;

    auto load_kv = [&](int buf, int k0) {
        uint32_t sbase = sb + FKV_BASE + buf * FKV_STAGE;
        #pragma unroll
        for (int t = 0; t < 2; ++t) {              // 0: Kh, 1: Vh
            const int coloff = (t == 0) ? DM : 2 * DM;
            #pragma unroll
            for (int p = 0; p < 2; ++p) {
                int idx = tid + p * 256;
                int r = idx >> 3;
                int c = (idx & 7) << 3;
                uint32_t off = (uint32_t)(r * 128 + c * 2);
                cp16(sbase + t * 8192 + SMEM_SWIZZLE_128B(off),
                     qkvh + (size_t)(b * S_LEN + k0 + r) * (3 * DM) + coloff + h * HDIM + c);
            }
        }
    };

    // Q tile into smem, swizzled
    #pragma unroll
    for (int p = 0; p < 4; ++p) {
        int idx = tid + p * 256;
        int r = idx >> 3;
        int c = (idx & 7) << 3;
        uint4 v = *reinterpret_cast<const uint4*>(
            qkvh + (size_t)(b * S_LEN + q0 + r) * (3 * DM) + h * HDIM + c);
        uint32_t off = (uint32_t)(r * 128 + c * 2);
        *reinterpret_cast<uint4*>(smem + FTS_Q + SMEM_SWIZZLE_128B(off)) = v;
    }
    load_kv(0, 0);
    CP_COMMIT();
    __syncthreads();

    const int a_row  = (lid & 7) + ((lid >> 3) & 1) * 8;
    const int a_koff = (lid >> 4) << 3;
    const int b_row  = ((lid >> 4) << 3) + (lid & 7);
    const int b_koff = ((lid >> 3) & 1) << 3;
    uint32_t qh[4][4];
    #pragma unroll
    for (int kk = 0; kk < 4; ++kk) {
        int rg = wid * 16 + a_row;
        uint32_t sw = (uint32_t)(rg * 128 + (kk * 16 + a_koff) * 2)
                      ^ ((uint32_t)(rg & 7) << 4);
        ldsm_x4(qh[kk], sb + FTS_Q + sw);
    }

    float o[8][4];
    #pragma unroll
    for (int j = 0; j < 8; ++j)
        #pragma unroll
        for (int r = 0; r < 4; ++r) o[j][r] = 0.0f;
    float mrow[2] = {-INFINITY, -INFINITY};
    float lrow[2] = {0.0f, 0.0f};

    const int g8 = lid >> 2, t2 = (lid & 3) * 2;
    const int nkt = 2 * qt + 2;

    for (int kt = 0; kt < nkt; ++kt) {
        const int k0 = kt * 64;
        CP_WAIT(0);
        __syncthreads();
        if (kt + 1 < nkt) {
            load_kv((kt + 1) & 1, (kt + 1) * 64);
            CP_COMMIT();
        }

        const uint32_t kvs = sb + FKV_BASE + (kt & 1) * FKV_STAGE;

        if (q0 + wid * 16 + 15 >= k0) {
            float s[8][4];
            #pragma unroll
            for (int j = 0; j < 8; ++j)
                #pragma unroll
                for (int r = 0; r < 4; ++r) s[j][r] = 0.0f;

            // S = Qh @ Kh^T (single pass)
            #pragma unroll
            for (int kk = 0; kk < 4; ++kk) {
                uint32_t kb[4][4];
                #pragma unroll
                for (int g = 0; g < 4; ++g) {
                    int rg = g * 16 + b_row;
                    uint32_t sw = (uint32_t)(rg * 128 + (kk * 16 + b_koff) * 2)
                                  ^ ((uint32_t)(rg & 7) << 4);
                    ldsm_x4(kb[g], kvs + sw);
                }
                #pragma unroll
                for (int g = 0; g < 4; ++g) {
                    mma_f16(s[2 * g],     qh[kk], kb[g][0], kb[g][1]);
                    mma_f16(s[2 * g + 1], qh[kk], kb[g][2], kb[g][3]);
                }
            }

            const bool diag = (k0 + 63 > q0 + wid * 16);
            #pragma unroll
            for (int j = 0; j < 8; ++j) {
                #pragma unroll
                for (int r2 = 0; r2 < 2; ++r2) {
                    int qrow = q0 + wid * 16 + g8 + 8 * r2;
                    #pragma unroll
                    for (int e = 0; e < 2; ++e) {
                        float v = s[j][2 * r2 + e] * 0.125f;
                        if (diag && (k0 + j * 8 + t2 + e > qrow)) v = -1e30f;
                        s[j][2 * r2 + e] = v;
                    }
                }
            }

            #pragma unroll
            for (int r2 = 0; r2 < 2; ++r2) {
                float mx = -INFINITY;
                #pragma unroll
                for (int j = 0; j < 8; ++j)
                    mx = fmaxf(mx, fmaxf(s[j][2 * r2], s[j][2 * r2 + 1]));
                mx = fmaxf(mx, __shfl_xor_sync(0xffffffffu, mx, 1));
                mx = fmaxf(mx, __shfl_xor_sync(0xffffffffu, mx, 2));
                float mnew = fmaxf(mrow[r2], mx);
                float alpha = fast_exp2((mrow[r2] - mnew) * LOG2E);
                mrow[r2] = mnew;
                float ls = 0.0f;
                #pragma unroll
                for (int j = 0; j < 8; ++j) {
                    float p0 = fast_exp2((s[j][2 * r2] - mnew) * LOG2E);
                    float p1 = fast_exp2((s[j][2 * r2 + 1] - mnew) * LOG2E);
                    s[j][2 * r2] = p0;
                    s[j][2 * r2 + 1] = p1;
                    ls += p0 + p1;
                }
                ls += __shfl_xor_sync(0xffffffffu, ls, 1);
                ls += __shfl_xor_sync(0xffffffffu, ls, 2);
                lrow[r2] = lrow[r2] * alpha + ls;
                #pragma unroll
                for (int j = 0; j < 8; ++j) {
                    o[j][2 * r2] *= alpha;
                    o[j][2 * r2 + 1] *= alpha;
                }
            }

            // O += Ph @ Vh (single pass)
            #pragma unroll
            for (int kk = 0; kk < 4; ++kk) {
                uint32_t ph[4];
                ph[0] = pack_h2(s[2 * kk][0],     s[2 * kk][1]);
                ph[1] = pack_h2(s[2 * kk][2],     s[2 * kk][3]);
                ph[2] = pack_h2(s[2 * kk + 1][0], s[2 * kk + 1][1]);
                ph[3] = pack_h2(s[2 * kk + 1][2], s[2 * kk + 1][3]);
                int vrow = kk * 16 + (lid & 7) + ((lid >> 3) & 1) * 8;
                uint32_t vb[4][4];
                #pragma unroll
                for (int j2 = 0; j2 < 4; ++j2) {
                    uint32_t sw = (uint32_t)(vrow * 128 + j2 * 32 + ((lid >> 4) & 1) * 16)
                                  ^ ((uint32_t)(vrow & 7) << 4);
                    ldsm_x4_t(vb[j2], kvs + 8192 + sw);
                }
                #pragma unroll
                for (int j2 = 0; j2 < 4; ++j2) {
                    mma_f16(o[2 * j2],     ph, vb[j2][0], vb[j2][1]);
                    mma_f16(o[2 * j2 + 1], ph, vb[j2][2], vb[j2][3]);
                }
            }
        }
    }

    float inv0 = 1.0f / lrow[0], inv1 = 1.0f / lrow[1];
    size_t row0 = (size_t)(b * S_LEN + q0 + wid * 16 + g8);
    #pragma unroll
    for (int j = 0; j < 8; ++j) {
        int c = h * HDIM + j * 8 + t2;
        *reinterpret_cast<uint32_t*>(&ctxh[row0 * DM + c]) =
            pack_h2(o[j][0] * inv0, o[j][1] * inv0);
        *reinterpret_cast<uint32_t*>(&ctxh[(row0 + 8) * DM + c]) =
            pack_h2(o[j][2] * inv1, o[j][3] * inv1);
    }
}

// ---------------------------------------------------------------------------
extern "C" void kernel_launch(void* const* d_in, const int* in_sizes, int n_in,
                              void* d_out, int out_size)
{
    const float* x    = (const float*)d_in[0];
    const float* Wqkv = (const float*)d_in[1];
    const float* bqkv = (const float*)d_in[2];
    const float* Wout = (const float*)d_in[3];
    const float* bout = (const float*)d_in[4];
    float* out = (float*)d_out;

    __half *qkvh, *xh, *ctxh, *wqh, *woh;
    cudaGetSymbolAddress((void**)&qkvh, g_qkvh);
    cudaGetSymbolAddress((void**)&xh, g_xh);
    cudaGetSymbolAddress((void**)&ctxh, g_ctxh);
    cudaGetSymbolAddress((void**)&wqh, g_wqkvTh);
    cudaGetSymbolAddress((void**)&woh, g_woutTh);

    cudaFuncSetAttribute(gemm_mma<0>, cudaFuncAttributeMaxDynamicSharedMemorySize, GEMM_SMEM);
    cudaFuncSetAttribute(gemm_mma<1>, cudaFuncAttributeMaxDynamicSharedMemorySize, GEMM_SMEM);
    cudaFuncSetAttribute(flash_tc, cudaFuncAttributeMaxDynamicSharedMemorySize, FLASH_SMEM_TC);

    // 0) Fused prologue: round x + transpose/round both weights (one launch)
    prologue<<<XB + QB + OB, 256>>>(x, xh, Wqkv, wqh, Wout, woh);

    // 1) QKV projection (single pass) -> fp16 qkv
    gemm_mma<1><<<dim3(3 * DM / 128, MROWS / 128), 256, GEMM_SMEM>>>(
        xh, wqh, bqkv, nullptr, qkvh, MROWS, 3 * DM, DM);

    // 2) Causal flash attention -> fp16 ctx
    flash_tc<<<dim3(BATCH * NHEADS, S_LEN / 128), 256, FLASH_SMEM_TC>>>(qkvh, ctxh);

    // 3) Output projection (single pass) -> f32 out
    gemm_mma<0><<<dim3(DM / 128, MROWS / 128), 256, GEMM_SMEM>>>(
        ctxh, woh, bout, out, nullptr, MROWS, DM, DM);
}